// round 3
// baseline (speedup 1.0000x reference)
#include <cuda_runtime.h>
#include <cuda_bf16.h>

#define PL_TOTAL (2048 * 256)   // 524288 occurrences
#define NNODES   50000
#define DIM      256

// Scratch (static device globals -- no allocation in kernel_launch)
__device__ __nv_bfloat16 g_qh[(size_t)NNODES * DIM];   // q in bf16 (L2-resident)
__device__ float g_agg[(size_t)NNODES * DIM];          // unnormalized numerator
__device__ float g_denom[NNODES];
__device__ int   g_mask_word;   // 1 = mask elements are 4-byte (f32/i32), 0 = 1-byte

// ---------------------------------------------------------------------------
// f32x2 packed-FMA helpers (sm_103a FFMA2; bitwise == two fmaf)
// ---------------------------------------------------------------------------
__device__ __forceinline__ void fma2(unsigned long long& d,
                                     unsigned long long a,
                                     unsigned long long b) {
    asm("fma.rn.f32x2 %0, %1, %2, %0;" : "+l"(d) : "l"(a), "l"(b));
}
__device__ __forceinline__ float f2lo(unsigned long long x) {
    return __uint_as_float((unsigned)x);
}
__device__ __forceinline__ float f2hi(unsigned long long x) {
    return __uint_as_float((unsigned)(x >> 32));
}

// ---------------------------------------------------------------------------
// Detect mask element width from raw bytes (deterministic).
// ---------------------------------------------------------------------------
__global__ void detect_mask_kernel(const unsigned char* __restrict__ m) {
    __shared__ int f32flag, oddflag;
    if (threadIdx.x == 0) { f32flag = 0; oddflag = 0; }
    __syncthreads();
    for (int i = threadIdx.x; i < 4096; i += blockDim.x) {
        unsigned char b = m[i];
        if (b == 0x3F && (i & 3) == 3) atomicOr(&f32flag, 1);
        if (b != 0 && (i & 3) != 0)    atomicOr(&oddflag, 1);
    }
    __syncthreads();
    if (threadIdx.x == 0)
        g_mask_word = (f32flag || !oddflag) ? 1 : 0;
}

// ---------------------------------------------------------------------------
// Zero the accumulators
// ---------------------------------------------------------------------------
__global__ void zero_kernel() {
    size_t i = (size_t)blockIdx.x * blockDim.x + threadIdx.x;
    size_t stride = (size_t)gridDim.x * blockDim.x;
    size_t total = (size_t)NNODES * DIM;
    for (size_t j = i; j < total; j += stride) g_agg[j] = 0.0f;
    for (size_t j = i; j < NNODES; j += stride) g_denom[j] = 0.0f;
}

// ---------------------------------------------------------------------------
// One-pass scatter attention: one warp per occurrence. q gathered as bf16.
// ---------------------------------------------------------------------------
__global__ __launch_bounds__(256)
void scatter_kernel(const float* __restrict__ enc,
                    const void* __restrict__ mask,
                    const int* __restrict__ idx) {
    int occ  = (int)((blockIdx.x * blockDim.x + threadIdx.x) >> 5);
    int lane = threadIdx.x & 31;
    if (occ >= PL_TOTAL) return;

    bool live;
    if (g_mask_word)
        live = ((const unsigned int*)mask)[occ] != 0u;
    else
        live = ((const unsigned char*)mask)[occ] != 0;
    if (!live) return;

    int node = idx[occ];
    const float4* e4 = (const float4*)(enc + (size_t)occ * DIM);
    const __nv_bfloat162* q2 = (const __nv_bfloat162*)(g_qh + (size_t)node * DIM);

    float4 e0 = e4[lane];
    float4 e1 = e4[lane + 32];
    float2 qa = __bfloat1622float2(q2[lane * 2]);
    float2 qb = __bfloat1622float2(q2[lane * 2 + 1]);
    float2 qc = __bfloat1622float2(q2[64 + lane * 2]);
    float2 qd = __bfloat1622float2(q2[64 + lane * 2 + 1]);

    float p = e0.x * qa.x + e0.y * qa.y + e0.z * qb.x + e0.w * qb.y
            + e1.x * qc.x + e1.y * qc.y + e1.z * qd.x + e1.w * qd.y;
#pragma unroll
    for (int o = 16; o; o >>= 1) p += __shfl_xor_sync(0xffffffffu, p, o);

    float w = __expf(p * 0.0625f);        // 1/sqrt(256) = 1/16

    float* base = g_agg + (size_t)node * DIM;
    float4 v0 = make_float4(w * e0.x, w * e0.y, w * e0.z, w * e0.w);
    float4 v1 = make_float4(w * e1.x, w * e1.y, w * e1.z, w * e1.w);

    asm volatile("red.global.add.v4.f32 [%0], {%1,%2,%3,%4};"
                 :: "l"(base + lane * 4),
                    "f"(v0.x), "f"(v0.y), "f"(v0.z), "f"(v0.w) : "memory");
    asm volatile("red.global.add.v4.f32 [%0], {%1,%2,%3,%4};"
                 :: "l"(base + 128 + lane * 4),
                    "f"(v1.x), "f"(v1.y), "f"(v1.z), "f"(v1.w) : "memory");

    if (lane == 0) atomicAdd(&g_denom[node], w);
}

// ---------------------------------------------------------------------------
// f32x2 SGEMM: C[M,256] = [A1 | A2/denom] @ W (+bias).
// MODE 0: KTOT=256, C = bf16 (q projection).
// MODE 1: KTOT=512, A2 normalized by g_denom on the fly, fused sigmoid gate:
//         out = z*A1 + (1-z)*A2n, z = sigmoid(S + bias), fp32 out.
// Tile 128x128, BK=8, 256 threads, 8x8 microtile via 32 FFMA2/kk.
// B tile stored value-duplicated so b-pairs load directly as 64-bit lanes.
// ---------------------------------------------------------------------------
template <int KTOT, int MODE>
__global__ __launch_bounds__(256)
void sgemm2_kernel(const float* __restrict__ A1,
                   const float* __restrict__ A2,
                   const float* __restrict__ W,
                   const float* __restrict__ bias,
                   void* __restrict__ Cout,
                   int M) {
    __shared__ float As[8][128];
    __shared__ float Bs2[8][256];   // duplicated: Bs2[k][2c]=Bs2[k][2c+1]=W[k][bn+c]

    const int tid = threadIdx.x;
    const int bm = blockIdx.x * 128;
    const int bn = blockIdx.y * 128;
    const int ty = tid >> 4;        // 0..15
    const int tx = tid & 15;        // 0..15

    // loader indices
    const int ar = tid >> 1;        // A row within tile (0..127)
    const int ac = (tid & 1) * 4;   // A k-offset (0 or 4)
    const int br = tid >> 5;        // B k row (0..7)
    const int bc = (tid & 31) * 4;  // B col (0..124)

    const int grow = bm + ar;
    float rdA = 1.0f;
    if (MODE == 1 && grow < M)
        rdA = 1.0f / (g_denom[grow] + 1e-9f);   // normalize agg on load

    unsigned long long acc[4][8];
#pragma unroll
    for (int i = 0; i < 4; i++)
#pragma unroll
        for (int j = 0; j < 8; j++) acc[i][j] = 0ULL;

    for (int k0 = 0; k0 < KTOT; k0 += 8) {
        const bool isA2 = (KTOT == 512) && (k0 >= 256);
        const float* Asrc = isA2 ? A2 : A1;
        const int kloc = k0 & 255;

        float4 av = make_float4(0.f, 0.f, 0.f, 0.f);
        if (grow < M)
            av = *(const float4*)(Asrc + (size_t)grow * 256 + kloc + ac);
        if (MODE == 1 && isA2) {
            av.x *= rdA; av.y *= rdA; av.z *= rdA; av.w *= rdA;
        }
        As[ac + 0][ar] = av.x;
        As[ac + 1][ar] = av.y;
        As[ac + 2][ar] = av.z;
        As[ac + 3][ar] = av.w;

        float4 bv = *(const float4*)(W + (size_t)(k0 + br) * 256 + bn + bc);
        float4 w0 = make_float4(bv.x, bv.x, bv.y, bv.y);
        float4 w1 = make_float4(bv.z, bv.z, bv.w, bv.w);
        *(float4*)&Bs2[br][bc * 2]     = w0;
        *(float4*)&Bs2[br][bc * 2 + 4] = w1;

        __syncthreads();

#pragma unroll
        for (int kk = 0; kk < 8; kk++) {
            ulonglong2 a0 = *(const ulonglong2*)&As[kk][ty * 4];
            ulonglong2 a1 = *(const ulonglong2*)&As[kk][64 + ty * 4];
            unsigned long long ap[4] = {a0.x, a0.y, a1.x, a1.y};
            ulonglong2 b0 = *(const ulonglong2*)&Bs2[kk][tx * 4];
            ulonglong2 b1 = *(const ulonglong2*)&Bs2[kk][64 + tx * 4];
            ulonglong2 b2 = *(const ulonglong2*)&Bs2[kk][128 + tx * 4];
            ulonglong2 b3 = *(const ulonglong2*)&Bs2[kk][192 + tx * 4];
            unsigned long long bp[8] = {b0.x, b0.y, b1.x, b1.y,
                                        b2.x, b2.y, b3.x, b3.y};
#pragma unroll
            for (int i = 0; i < 4; i++)
#pragma unroll
                for (int j = 0; j < 8; j++)
                    fma2(acc[i][j], ap[i], bp[j]);
        }
        __syncthreads();
    }

    // Epilogue. acc[ip][2c+t]: lo/hi = row pair; col n = bn + c*32 + 2tx + t.
#pragma unroll
    for (int ip = 0; ip < 4; ip++) {
        int base_m = (ip < 2) ? (bm + ty * 4 + ip * 2)
                              : (bm + 64 + ty * 4 + (ip - 2) * 2);
#pragma unroll
        for (int h = 0; h < 2; h++) {
            int m = base_m + h;
            if (m >= M) continue;
            float rdm = 0.0f;
            if (MODE == 1) rdm = 1.0f / (g_denom[m] + 1e-9f);
#pragma unroll
            for (int c = 0; c < 4; c++) {
                int n = bn + c * 32 + 2 * tx;
                unsigned long long p0 = acc[ip][2 * c];
                unsigned long long p1 = acc[ip][2 * c + 1];
                float v0 = h ? f2hi(p0) : f2lo(p0);
                float v1 = h ? f2hi(p1) : f2lo(p1);
                if (MODE == 0) {
                    __nv_bfloat16* q = (__nv_bfloat16*)Cout;
                    *(__nv_bfloat162*)(q + (size_t)m * 256 + n) =
                        __floats2bfloat162_rn(v0, v1);
                } else {
                    float* C = (float*)Cout;
                    float2 bb = *(const float2*)(bias + n);
                    float2 pv = *(const float2*)(A1 + (size_t)m * 256 + n);
                    float2 ag = *(const float2*)(A2 + (size_t)m * 256 + n);
                    ag.x *= rdm; ag.y *= rdm;
                    float z0 = 1.0f / (1.0f + __expf(-(v0 + bb.x)));
                    float z1 = 1.0f / (1.0f + __expf(-(v1 + bb.y)));
                    float2 o;
                    o.x = z0 * pv.x + (1.0f - z0) * ag.x;
                    o.y = z1 * pv.y + (1.0f - z1) * ag.y;
                    *(float2*)(C + (size_t)m * 256 + n) = o;
                }
            }
        }
    }
}

// ---------------------------------------------------------------------------
// Launch
// Inputs: 0 encoded_paths f32 [2048,256,256], 1 paths_mask (autodetected),
// 2 paths_node_indices i32, 3 previous_encodings f32 [50000,256],
// 4 Wq f32 [256,256], 5 Wg f32 [512,256], 6 bg f32 [256], 7 nr_cfg_nodes
// ---------------------------------------------------------------------------
extern "C" void kernel_launch(void* const* d_in, const int* in_sizes, int n_in,
                              void* d_out, int out_size) {
    const float* enc          = (const float*)d_in[0];
    const void*  mask         = d_in[1];
    const int* idx            = (const int*)d_in[2];
    const float* prev         = (const float*)d_in[3];
    const float* Wq           = (const float*)d_in[4];
    const float* Wg           = (const float*)d_in[5];
    const float* bg           = (const float*)d_in[6];
    float* out                = (float*)d_out;

    void *qp = nullptr, *aggp = nullptr;
    cudaGetSymbolAddress(&qp, g_qh);
    cudaGetSymbolAddress(&aggp, g_agg);
    __nv_bfloat16* q_buf = (__nv_bfloat16*)qp;
    float* agg_buf       = (float*)aggp;

    const int M = NNODES;
    dim3 grid((M + 127) / 128, 2);

    // 0) detect mask element width
    detect_mask_kernel<<<1, 256>>>((const unsigned char*)mask);

    // 1) zero accumulators
    zero_kernel<<<2048, 256>>>();

    // 2) q = bf16(prev @ Wq)
    sgemm2_kernel<256, 0><<<grid, 256>>>(prev, prev, Wq, nullptr, q_buf, M);

    // 3) one-pass scatter softmax numerator/denominator
    scatter_kernel<<<PL_TOTAL / 8, 256>>>(enc, mask, idx);

    // 4) fused: out = z*prev + (1-z)*(agg/denom), z = sigmoid([prev|agg/denom]@Wg+bg)
    sgemm2_kernel<512, 1><<<grid, 256>>>(prev, agg_buf, Wg, bg, out, M);
}

// round 5
// speedup vs baseline: 1.8374x; 1.8374x over previous
#include <cuda_runtime.h>
#include <cuda_bf16.h>

#define PL_TOTAL (2048 * 256)   // 524288 occurrences
#define NNODES   50000
#define DIM      256

// Scratch (static device globals -- no allocation in kernel_launch)
__device__ __align__(32) float g_q[(size_t)NNODES * DIM];
__device__ __align__(16) float g_agg[(size_t)NNODES * DIM];
__device__ float g_denom[NNODES];
__device__ int   g_mask_word;   // 1 = mask elements are 4-byte (f32/i32), 0 = 1-byte

// ---------------------------------------------------------------------------
// Detect mask element width from raw bytes (deterministic).
// ---------------------------------------------------------------------------
__global__ void detect_mask_kernel(const unsigned char* __restrict__ m) {
    __shared__ int f32flag, oddflag;
    if (threadIdx.x == 0) { f32flag = 0; oddflag = 0; }
    __syncthreads();
    for (int i = threadIdx.x; i < 4096; i += blockDim.x) {
        unsigned char b = m[i];
        if (b == 0x3F && (i & 3) == 3) atomicOr(&f32flag, 1);
        if (b != 0 && (i & 3) != 0)    atomicOr(&oddflag, 1);
    }
    __syncthreads();
    if (threadIdx.x == 0)
        g_mask_word = (f32flag || !oddflag) ? 1 : 0;
}

// ---------------------------------------------------------------------------
// Zero the accumulators
// ---------------------------------------------------------------------------
__global__ void zero_kernel() {
    size_t i = (size_t)blockIdx.x * blockDim.x + threadIdx.x;
    size_t stride = (size_t)gridDim.x * blockDim.x;
    size_t total = (size_t)NNODES * DIM;
    for (size_t j = i; j < total; j += stride) g_agg[j] = 0.0f;
    for (size_t j = i; j < NNODES; j += stride) g_denom[j] = 0.0f;
}

// ---------------------------------------------------------------------------
// One-pass scatter attention: one warp per occurrence; each lane owns one
// contiguous 8-float (32B) chunk of the 256-dim row.
// enc is a 410MB stream -> .cs (evict-first). q (51MB) fits L2 -> evict_last
// (encoded as v4.b64, the only form ptxas accepts the hint on).
// ---------------------------------------------------------------------------
__global__ __launch_bounds__(256)
void scatter_kernel(const float* __restrict__ enc,
                    const void* __restrict__ mask,
                    const int* __restrict__ idx) {
    int occ  = (int)((blockIdx.x * blockDim.x + threadIdx.x) >> 5);
    int lane = threadIdx.x & 31;
    if (occ >= PL_TOTAL) return;

    bool live;
    if (g_mask_word)
        live = ((const unsigned int*)mask)[occ] != 0u;
    else
        live = ((const unsigned char*)mask)[occ] != 0;
    if (!live) return;

    int node = idx[occ];
    const float* ep = enc + (size_t)occ * DIM + lane * 8;
    const float* qp = g_q + (size_t)node * DIM + lane * 8;

    float4 e0, e1;
    asm volatile("ld.global.cs.v4.f32 {%0,%1,%2,%3}, [%4];"
                 : "=f"(e0.x), "=f"(e0.y), "=f"(e0.z), "=f"(e0.w) : "l"(ep));
    asm volatile("ld.global.cs.v4.f32 {%0,%1,%2,%3}, [%4];"
                 : "=f"(e1.x), "=f"(e1.y), "=f"(e1.z), "=f"(e1.w) : "l"(ep + 4));

    unsigned long long d0, d1, d2, d3;   // 8 q floats in one 32B load
    asm volatile("ld.global.L2::evict_last.v4.b64 {%0,%1,%2,%3}, [%4];"
                 : "=l"(d0), "=l"(d1), "=l"(d2), "=l"(d3) : "l"(qp));
    float q0x = __uint_as_float((unsigned)d0);
    float q0y = __uint_as_float((unsigned)(d0 >> 32));
    float q0z = __uint_as_float((unsigned)d1);
    float q0w = __uint_as_float((unsigned)(d1 >> 32));
    float q1x = __uint_as_float((unsigned)d2);
    float q1y = __uint_as_float((unsigned)(d2 >> 32));
    float q1z = __uint_as_float((unsigned)d3);
    float q1w = __uint_as_float((unsigned)(d3 >> 32));

    float p = e0.x * q0x + e0.y * q0y + e0.z * q0z + e0.w * q0w
            + e1.x * q1x + e1.y * q1y + e1.z * q1z + e1.w * q1w;
#pragma unroll
    for (int o = 16; o; o >>= 1) p += __shfl_xor_sync(0xffffffffu, p, o);

    float w = __expf(p * 0.0625f);        // 1/sqrt(256) = 1/16

    float* base = g_agg + (size_t)node * DIM + lane * 8;
    float4 v0 = make_float4(w * e0.x, w * e0.y, w * e0.z, w * e0.w);
    float4 v1 = make_float4(w * e1.x, w * e1.y, w * e1.z, w * e1.w);

    asm volatile("red.global.add.v4.f32 [%0], {%1,%2,%3,%4};"
                 :: "l"(base),
                    "f"(v0.x), "f"(v0.y), "f"(v0.z), "f"(v0.w) : "memory");
    asm volatile("red.global.add.v4.f32 [%0], {%1,%2,%3,%4};"
                 :: "l"(base + 4),
                    "f"(v1.x), "f"(v1.y), "f"(v1.z), "f"(v1.w) : "memory");

    if (lane == 0) atomicAdd(&g_denom[node], w);
}

// ---------------------------------------------------------------------------
// TF32 tensor-core GEMM: C[M,256] = [A1 | A2/denom] @ W (+bias).
//   MODE 0: KTOT=256, C = fp32 q projection.
//   MODE 1: KTOT=512, A2 scaled by 1/(denom+1e-9) on load, fused gate epilogue:
//           out = z*A1 + (1-z)*A2n, z = sigmoid(S + bias).
// Block tile 128x128, K-chunk 32, 256 threads = 8 warps (4 along M x 2 along N),
// warp tile 32x64 = 2x8 m16n8k8 mma tiles. fp32 accumulate, cvt.rna in loaders.
// ---------------------------------------------------------------------------
__device__ __forceinline__ unsigned cvt_tf32(float x) {
    unsigned u;
    asm("cvt.rna.tf32.f32 %0, %1;" : "=r"(u) : "f"(x));
    return u;
}

template <int KTOT, int MODE>
__global__ __launch_bounds__(256)
void tf32_gemm_kernel(const float* __restrict__ A1,
                      const float* __restrict__ A2,
                      const float* __restrict__ W,
                      const float* __restrict__ bias,
                      float* __restrict__ Cout,
                      int M) {
    __shared__ unsigned As[128][36];   // [m][k] tf32 bits, pad 36
    __shared__ unsigned Bs[32][132];   // [k][n] tf32 bits, pad 132

    const int tid  = threadIdx.x;
    const int bm   = blockIdx.x * 128;
    const int bn   = blockIdx.y * 128;
    const int warp = tid >> 5;
    const int lane = tid & 31;
    const int wm   = (warp & 3) * 32;   // warp M offset in tile
    const int wn   = (warp >> 2) * 64;  // warp N offset in tile
    const int r    = lane >> 2;         // 0..7
    const int kq   = lane & 3;          // 0..3

    float c[2][8][4];
#pragma unroll
    for (int i = 0; i < 2; i++)
#pragma unroll
        for (int j = 0; j < 8; j++)
#pragma unroll
            for (int t = 0; t < 4; t++) c[i][j][t] = 0.0f;

    for (int k0 = 0; k0 < KTOT; k0 += 32) {
        const bool isA2 = (KTOT == 512) && (k0 >= 256);
        const float* Asrc = isA2 ? A2 : A1;
        const int kloc = k0 & 255;

        // --- load A tile: 128 rows x 32 cols = 1024 float4 ---
#pragma unroll
        for (int j = 0; j < 4; j++) {
            int i = tid + j * 256;          // 0..1023
            int row = i >> 3;               // 0..127
            int c4  = i & 7;                // 0..7
            int grow = bm + row; if (grow >= M) grow = M - 1;
            float4 av = *(const float4*)(Asrc + (size_t)grow * 256 + kloc + c4 * 4);
            if (MODE == 1 && isA2) {
                float rd = 1.0f / (g_denom[grow] + 1e-9f);
                av.x *= rd; av.y *= rd; av.z *= rd; av.w *= rd;
            }
            uint4 tv = make_uint4(cvt_tf32(av.x), cvt_tf32(av.y),
                                  cvt_tf32(av.z), cvt_tf32(av.w));
            *(uint4*)&As[row][c4 * 4] = tv;
        }
        // --- load B tile: 32 rows x 128 cols = 1024 float4 ---
#pragma unroll
        for (int j = 0; j < 4; j++) {
            int i = tid + j * 256;
            int krow = i >> 5;              // 0..31
            int c4   = i & 31;              // 0..31
            float4 bv = *(const float4*)(W + (size_t)(k0 + krow) * 256 + bn + c4 * 4);
            uint4 tv = make_uint4(cvt_tf32(bv.x), cvt_tf32(bv.y),
                                  cvt_tf32(bv.z), cvt_tf32(bv.w));
            *(uint4*)&Bs[krow][c4 * 4] = tv;
        }
        __syncthreads();

#pragma unroll
        for (int kk = 0; kk < 4; kk++) {   // 4 k8 steps
            unsigned a[2][4];
#pragma unroll
            for (int mt = 0; mt < 2; mt++) {
                int m = wm + mt * 16;
                a[mt][0] = As[m + r][kk * 8 + kq];
                a[mt][1] = As[m + r + 8][kk * 8 + kq];
                a[mt][2] = As[m + r][kk * 8 + kq + 4];
                a[mt][3] = As[m + r + 8][kk * 8 + kq + 4];
            }
            unsigned b[8][2];
#pragma unroll
            for (int nt = 0; nt < 8; nt++) {
                int n = wn + nt * 8;
                b[nt][0] = Bs[kk * 8 + kq][n + r];
                b[nt][1] = Bs[kk * 8 + kq + 4][n + r];
            }
#pragma unroll
            for (int mt = 0; mt < 2; mt++)
#pragma unroll
                for (int nt = 0; nt < 8; nt++) {
                    asm volatile(
                        "mma.sync.aligned.m16n8k8.row.col.f32.tf32.tf32.f32 "
                        "{%0,%1,%2,%3}, {%4,%5,%6,%7}, {%8,%9}, {%0,%1,%2,%3};"
                        : "+f"(c[mt][nt][0]), "+f"(c[mt][nt][1]),
                          "+f"(c[mt][nt][2]), "+f"(c[mt][nt][3])
                        : "r"(a[mt][0]), "r"(a[mt][1]), "r"(a[mt][2]), "r"(a[mt][3]),
                          "r"(b[nt][0]), "r"(b[nt][1]));
                }
        }
        __syncthreads();
    }

    // --- epilogue ---
#pragma unroll
    for (int mt = 0; mt < 2; mt++) {
#pragma unroll
        for (int h = 0; h < 2; h++) {      // row r / row r+8
            int m = bm + wm + mt * 16 + r + h * 8;
            if (m >= M) continue;
            float rdm = 0.0f;
            if (MODE == 1) rdm = 1.0f / (g_denom[m] + 1e-9f);
#pragma unroll
            for (int nt = 0; nt < 8; nt++) {
                int n = bn + wn + nt * 8 + 2 * kq;
                float v0 = c[mt][nt][h * 2 + 0];
                float v1 = c[mt][nt][h * 2 + 1];
                if (MODE == 0) {
                    *(float2*)(Cout + (size_t)m * 256 + n) = make_float2(v0, v1);
                } else {
                    float2 bb = *(const float2*)(bias + n);
                    float2 pv = *(const float2*)(A1 + (size_t)m * 256 + n);
                    float2 ag = *(const float2*)(A2 + (size_t)m * 256 + n);
                    ag.x *= rdm; ag.y *= rdm;
                    float z0 = 1.0f / (1.0f + __expf(-(v0 + bb.x)));
                    float z1 = 1.0f / (1.0f + __expf(-(v1 + bb.y)));
                    float2 o;
                    o.x = z0 * pv.x + (1.0f - z0) * ag.x;
                    o.y = z1 * pv.y + (1.0f - z1) * ag.y;
                    *(float2*)(Cout + (size_t)m * 256 + n) = o;
                }
            }
        }
    }
}

// ---------------------------------------------------------------------------
// Launch
// Inputs: 0 encoded_paths f32 [2048,256,256], 1 paths_mask (autodetected),
// 2 paths_node_indices i32, 3 previous_encodings f32 [50000,256],
// 4 Wq f32 [256,256], 5 Wg f32 [512,256], 6 bg f32 [256], 7 nr_cfg_nodes
// ---------------------------------------------------------------------------
extern "C" void kernel_launch(void* const* d_in, const int* in_sizes, int n_in,
                              void* d_out, int out_size) {
    const float* enc  = (const float*)d_in[0];
    const void*  mask = d_in[1];
    const int*   idx  = (const int*)d_in[2];
    const float* prev = (const float*)d_in[3];
    const float* Wq   = (const float*)d_in[4];
    const float* Wg   = (const float*)d_in[5];
    const float* bg   = (const float*)d_in[6];
    float* out        = (float*)d_out;

    void *qp = nullptr, *aggp = nullptr;
    cudaGetSymbolAddress(&qp, g_q);
    cudaGetSymbolAddress(&aggp, g_agg);
    float* q_buf   = (float*)qp;
    float* agg_buf = (float*)aggp;

    const int M = NNODES;
    dim3 grid((M + 127) / 128, 2);

    // 0) detect mask element width
    detect_mask_kernel<<<1, 256>>>((const unsigned char*)mask);

    // 1) zero accumulators
    zero_kernel<<<2048, 256>>>();

    // 2) q = prev @ Wq  (tf32 tensor cores, fp32 out)
    tf32_gemm_kernel<256, 0><<<grid, 256>>>(prev, prev, Wq, nullptr, q_buf, M);

    // 3) one-pass scatter softmax numerator/denominator
    scatter_kernel<<<PL_TOTAL / 8, 256>>>(enc, mask, idx);

    // 4) fused: out = z*prev + (1-z)*(agg/denom), z = sigmoid([prev|agg/denom]@Wg+bg)
    tf32_gemm_kernel<512, 1><<<grid, 256>>>(prev, agg_buf, Wg, bg, out, M);
}